// round 9
// baseline (speedup 1.0000x reference)
#include <cuda_runtime.h>
#include <cuda_bf16.h>
#include <cstdint>

#define NB 32
#define NL 128
#define ND 512
#define NROWS (NB*NL)   // 4096

// ================= scratch (device code references ONLY — GB300 ATS trap) =================
__device__ float g_wq_new[NROWS*ND];
__device__ float g_wq_cur[NROWS*ND];
__device__ float g_uh_new[NROWS*ND];
__device__ float g_uh_cur[NROWS*ND];
__device__ float g_c1[NROWS*ND];
__device__ float g_c2[NROWS*ND];

__device__ __nv_bfloat16 g_Wqt_hi[ND*ND];      // Wq^T  [N=512][K=512]
__device__ __nv_bfloat16 g_Wqt_lo[ND*ND];
__device__ __nv_bfloat16 g_Wct_hi[ND*ND];
__device__ __nv_bfloat16 g_Wct_lo[ND*ND];
__device__ __nv_bfloat16 g_Wot_hi[ND*2*ND];    // Wout^T [N=512][K=1024]
__device__ __nv_bfloat16 g_Wot_lo[ND*2*ND];

// ================= helpers =================
__device__ __forceinline__ uint32_t smem_u32(const void* p){
    uint32_t a;
    asm("{ .reg .u64 t; cvta.to.shared.u64 t, %1; cvt.u32.u64 %0, t; }" : "=r"(a) : "l"(p));
    return a;
}
__device__ __forceinline__ float tanh_apx(float x){
    float y; asm("tanh.approx.f32 %0, %1;" : "=f"(y) : "f"(x)); return y;
}
__device__ __forceinline__ void split2(float x, __nv_bfloat16& h, __nv_bfloat16& l){
    h = __float2bfloat16_rn(x);
    l = __float2bfloat16_rn(x - __bfloat162float(h));
}
__device__ __forceinline__ uint32_t lds32(uint32_t a){
    uint32_t v; asm volatile("ld.shared.b32 %0, [%1];" : "=r"(v) : "r"(a)); return v;
}
__device__ __forceinline__ void mma16816(float* c, const uint32_t* a, const uint32_t* b){
    asm volatile("mma.sync.aligned.m16n8k16.row.col.f32.bf16.bf16.f32 "
        "{%0,%1,%2,%3},{%4,%5,%6,%7},{%8,%9},{%0,%1,%2,%3};"
        : "+f"(c[0]),"+f"(c[1]),"+f"(c[2]),"+f"(c[3])
        : "r"(a[0]),"r"(a[1]),"r"(a[2]),"r"(a[3]),"r"(b[0]),"r"(b[1]));
}
__device__ __forceinline__ void split_pack8(const float* f, uint4& uh, uint4& ul){
    uint32_t hs[8], ls[8];
    #pragma unroll
    for (int j=0;j<8;j++){
        __nv_bfloat16 h,l; split2(f[j],h,l);
        hs[j] = (uint32_t)__bfloat16_as_ushort(h);
        ls[j] = (uint32_t)__bfloat16_as_ushort(l);
    }
    uh.x = hs[0]|(hs[1]<<16); uh.y = hs[2]|(hs[3]<<16);
    uh.z = hs[4]|(hs[5]<<16); uh.w = hs[6]|(hs[7]<<16);
    ul.x = ls[0]|(ls[1]<<16); ul.y = ls[2]|(ls[3]<<16);
    ul.z = ls[4]|(ls[5]<<16); ul.w = ls[6]|(ls[7]<<16);
}

// ================= weight transpose+split (selector-based) =================
// in[R][C] fp32 -> out[C][R] hi/lo bf16. grid (C/32, R/32), block (32,8)
__global__ void __launch_bounds__(256) splitT_kernel(
    const float* __restrict__ in, int which, int R, int C)
{
    __nv_bfloat16 *hi, *lo;
    if      (which == 0){ hi = g_Wqt_hi; lo = g_Wqt_lo; }
    else if (which == 1){ hi = g_Wct_hi; lo = g_Wct_lo; }
    else                { hi = g_Wot_hi; lo = g_Wot_lo; }
    __shared__ float t[32][33];
    int bx = blockIdx.x*32, by = blockIdx.y*32;
    int x = threadIdx.x, y = threadIdx.y;
    #pragma unroll
    for (int i=0;i<32;i+=8)
        t[y+i][x] = in[(size_t)(by+y+i)*C + bx + x];
    __syncthreads();
    #pragma unroll
    for (int i=0;i<32;i+=8){
        float v = t[x][y+i];
        __nv_bfloat16 h,l; split2(v,h,l);
        size_t o = (size_t)(bx+y+i)*R + by + x;
        hi[o]=h; lo[o]=l;
    }
}

// ================= split-bf16 GEMM core (fp32 A, on-the-fly split) =================
// C[128,128] tile = splitbf16(lerp(p1,p2)) @ B^T; 3-pass hi/lo, fp32 accum.
// 8 warps: warp (wm=wid&1, wn=wid>>1) owns 64x32. BK=32, single smem stage,
// register prefetch of next chunk. Fragment/mma core identical to R8 (verified).
#define BK    32
#define LDSW  40                 // padded row length (bf16 elems): 80B stride
#define MATE  (128*LDSW)         // elems per matrix tile (5120)
#define GSMEM (4*MATE*2)         // 40960 B

template<bool LERP, bool ACCUM>
__device__ __forceinline__ void gemm_core(
    const float* __restrict__ p1, const float* __restrict__ p2, float mval, int lda,
    const __nv_bfloat16* __restrict__ Bhi, const __nv_bfloat16* __restrict__ Blo,
    int ldb, int bk0,
    const float* __restrict__ bias, float* __restrict__ C, int ldc,
    int m0, int n0, int K)
{
    extern __shared__ char dsm[];
    __nv_bfloat16* sm = (__nv_bfloat16*)dsm;
    uint32_t sb = smem_u32(sm);
    int tid = threadIdx.x, lane = tid & 31, wid = tid >> 5;
    int wm = wid & 1, wn = wid >> 1;
    int g = lane >> 2, tig = lane & 3;

    float acc[4][4][4];
    #pragma unroll
    for (int i=0;i<4;i++)
        #pragma unroll
        for (int j=0;j<4;j++)
            #pragma unroll
            for (int k=0;k<4;k++) acc[i][j][k]=0.f;

    const int chunks = K / BK;
    uint4 sAh[2], sAl[2], sBh[2], sBl[2];

    // ---- prefetch chunk (A fp32 -> lerp -> split; B bf16 direct) ----
    #define PREFETCH(k0) do{                                                    \
        _Pragma("unroll")                                                       \
        for (int i=0;i<2;i++){                                                  \
            int cc = tid + i*256, row = cc>>2, kc = cc&3;                       \
            const float* r1 = p1 + (size_t)(m0+row)*lda + (k0) + kc*8;          \
            float4 xa = *(const float4*)r1;                                     \
            float4 xb = *(const float4*)(r1+4);                                 \
            float f[8] = {xa.x,xa.y,xa.z,xa.w, xb.x,xb.y,xb.z,xb.w};            \
            if (LERP){                                                          \
                const float* r2 = p2 + (size_t)(m0+row)*lda + (k0) + kc*8;      \
                float4 ya = *(const float4*)r2;                                 \
                float4 yb = *(const float4*)(r2+4);                             \
                float h[8] = {ya.x,ya.y,ya.z,ya.w, yb.x,yb.y,yb.z,yb.w};        \
                _Pragma("unroll")                                               \
                for (int j=0;j<8;j++) f[j] += mval*(h[j]-f[j]);                 \
            }                                                                   \
            split_pack8(f, sAh[i], sAl[i]);                                     \
        }                                                                       \
        _Pragma("unroll")                                                       \
        for (int i=0;i<2;i++){                                                  \
            int cc = tid + i*256, row = cc>>2, kc = cc&3;                       \
            size_t bo = (size_t)(n0+row)*ldb + bk0 + (k0) + kc*8;               \
            sBh[i] = *(const uint4*)(Bhi + bo);                                 \
            sBl[i] = *(const uint4*)(Blo + bo);                                 \
        }                                                                       \
    }while(0)

    PREFETCH(0);

    for (int c = 0; c < chunks; c++){
        __syncthreads();
        #pragma unroll
        for (int i=0;i<2;i++){
            int cc = tid + i*256, row = cc>>2, kc = cc&3;
            *(uint4*)(sm + 0*MATE + row*LDSW + kc*8) = sAh[i];
            *(uint4*)(sm + 1*MATE + row*LDSW + kc*8) = sAl[i];
            *(uint4*)(sm + 2*MATE + row*LDSW + kc*8) = sBh[i];
            *(uint4*)(sm + 3*MATE + row*LDSW + kc*8) = sBl[i];
        }
        __syncthreads();
        if (c+1 < chunks) PREFETCH((c+1)*BK);

        #pragma unroll
        for (int ks=0; ks<2; ks++){
            uint32_t ah[4][4], al[4][4], bh[4][2], bl[4][2];
            // A frags: a0=(g,2t) a1=(g+8,2t) a2=(g,2t+8) a3=(g+8,2t+8)
            #pragma unroll
            for (int mt=0;mt<4;mt++){
                uint32_t o00 = (uint32_t)((wm*64 + mt*16 + g)*LDSW + ks*16 + tig*2)*2;
                uint32_t o10 = o00 + 8*LDSW*2;
                uint32_t aH = sb + 0*MATE*2, aL = sb + 1*MATE*2;
                ah[mt][0] = lds32(aH + o00);
                ah[mt][1] = lds32(aH + o10);
                ah[mt][2] = lds32(aH + o00 + 16);
                ah[mt][3] = lds32(aH + o10 + 16);
                al[mt][0] = lds32(aL + o00);
                al[mt][1] = lds32(aL + o10);
                al[mt][2] = lds32(aL + o00 + 16);
                al[mt][3] = lds32(aL + o10 + 16);
            }
            // B frags (B^T stored [n][k]): b0=(k=2t,n=g) b1=(k=2t+8,n=g)
            #pragma unroll
            for (int nt=0;nt<4;nt++){
                uint32_t o0 = (uint32_t)((wn*32 + nt*8 + g)*LDSW + ks*16 + tig*2)*2;
                uint32_t bH = sb + 2*MATE*2, bL = sb + 3*MATE*2;
                bh[nt][0] = lds32(bH + o0);
                bh[nt][1] = lds32(bH + o0 + 16);
                bl[nt][0] = lds32(bL + o0);
                bl[nt][1] = lds32(bL + o0 + 16);
            }
            #pragma unroll
            for (int mt=0;mt<4;mt++)
                #pragma unroll
                for (int nt=0;nt<4;nt++){
                    mma16816(acc[mt][nt], ah[mt], bh[nt]);
                    mma16816(acc[mt][nt], ah[mt], bl[nt]);
                    mma16816(acc[mt][nt], al[mt], bh[nt]);
                }
        }
    }
    #undef PREFETCH

    // epilogue: c0,c1 -> (g, 2t..2t+1); c2,c3 -> (g+8, 2t..2t+1)
    int t2 = tig*2;
    #pragma unroll
    for (int mt=0;mt<4;mt++){
        int m = m0 + wm*64 + mt*16 + g;
        #pragma unroll
        for (int nt=0;nt<4;nt++){
            int n = n0 + wn*32 + nt*8 + t2;
            float2 r0, r1;
            r0.x = acc[mt][nt][0]; r0.y = acc[mt][nt][1];
            r1.x = acc[mt][nt][2]; r1.y = acc[mt][nt][3];
            float* c0p = C + (size_t)m*ldc + n;
            float* c1p = C + (size_t)(m+8)*ldc + n;
            if (ACCUM){
                float2 o0 = *(float2*)c0p, o1 = *(float2*)c1p;
                r0.x += o0.x; r0.y += o0.y;
                r1.x += o1.x; r1.y += o1.y;
            } else if (bias){
                float b0v = bias[n], b1v = bias[n+1];
                r0.x += b0v; r0.y += b1v;
                r1.x += b0v; r1.y += b1v;
            }
            *(float2*)c0p = r0;
            *(float2*)c1p = r1;
        }
    }
}

// proj combos: z=0: no@Wq+bq ; 1: cur@Wq+bq ; 2: no@Wc ; 3: cur@Wc
__global__ void __launch_bounds__(256) gemm_proj_kernel(
    const float* __restrict__ no, const float* __restrict__ cur, const float* __restrict__ bq)
{
    int z = blockIdx.z;
    const float* A = (z & 1) ? cur : no;
    const __nv_bfloat16* Bh = (z < 2) ? g_Wqt_hi : g_Wct_hi;
    const __nv_bfloat16* Bl = (z < 2) ? g_Wqt_lo : g_Wct_lo;
    float* C = (z==0)?g_wq_new:(z==1)?g_wq_cur:(z==2)?g_uh_new:g_uh_cur;
    const float* bias = (z < 2) ? bq : nullptr;
    gemm_core<false,false>(A, nullptr, 0.f, ND, Bh, Bl, ND, 0,
                           bias, C, ND, blockIdx.x*128, blockIdx.y*128, ND);
}

// final accumulate GEMM: out += mix(c1,c2) @ Wout[0:512]
__global__ void __launch_bounds__(256) gemm_out2_kernel(
    const float* __restrict__ mixp, float* __restrict__ out)
{
    int gg = blockIdx.x;
    float m = __ldg(mixp);
    gemm_core<true,true>(g_c1, g_c2, m, ND, g_Wot_hi, g_Wot_lo, 2*ND, 0,
                         nullptr, out, ND, (gg>>2)*128, (gg&3)*128, ND);
}

// ================= fused attention + out-half1 (block-specialized) =================
// 1152 blocks: bz%9==8 -> GEMM tile of out = mix(no,cur)@Wout[512:1024] + bout (128 tiles);
// else attention (1024 blocks).
__global__ void __launch_bounds__(256) attn_out1_kernel(
    const float* __restrict__ cur, const float* __restrict__ no,
    const float* __restrict__ v, const float* __restrict__ bout,
    const float* __restrict__ mixp, float* __restrict__ out)
{
    int bz = blockIdx.x;
    if ((bz % 9) == 8){
        int gg = bz / 9;    // 0..127
        float m = __ldg(mixp);
        gemm_core<true,false>(no, cur, m, ND, g_Wot_hi, g_Wot_lo, 2*ND, ND,
                              bout, out, ND, (gg>>2)*128, (gg&3)*128, ND);
        return;
    }
    int a = bz - bz/9;      // 0..1023
    int dir = a >> 9;
    int bb  = (a >> 4) & 31;
    int t0  = (a & 15) * 8;

    extern __shared__ char dsm[];
    float* sc = (float*)dsm;              // [8][128]
    float* pm = (float*)(dsm + 4096);     // [128][8]

    const float* wq  = dir ? g_wq_cur : g_wq_new;
    const float* uh  = dir ? g_uh_new : g_uh_cur;
    const float* mem = dir ? no       : cur;
    float*       cO  = dir ? g_c2     : g_c1;

    int tid = threadIdx.x, w = tid >> 5, lane = tid & 31;

    float4 v4[4], q4[4];
    {
        const float* wrow = wq + (size_t)(bb*NL + t0 + w)*ND;
        #pragma unroll
        for (int i=0;i<4;i++){
            v4[i] = *(const float4*)(v    + lane*4 + 128*i);
            q4[i] = *(const float4*)(wrow + lane*4 + 128*i);
        }
    }
    for (int s=0; s<NL; s++){
        const float* urow = uh + (size_t)(bb*NL + s)*ND;
        float acc = 0.f;
        #pragma unroll
        for (int i=0;i<4;i++){
            float4 u = *(const float4*)(urow + lane*4 + 128*i);
            acc += v4[i].x * tanh_apx(q4[i].x + u.x);
            acc += v4[i].y * tanh_apx(q4[i].y + u.y);
            acc += v4[i].z * tanh_apx(q4[i].z + u.z);
            acc += v4[i].w * tanh_apx(q4[i].w + u.w);
        }
        #pragma unroll
        for (int off=16; off; off>>=1)
            acc += __shfl_xor_sync(0xffffffffu, acc, off);
        if (lane == 0) sc[w*NL + s] = acc;
    }
    __syncwarp();

    {
        float sv[4];
        #pragma unroll
        for (int i=0;i<4;i++) sv[i] = sc[w*NL + lane + 32*i];
        float mx = fmaxf(fmaxf(sv[0],sv[1]), fmaxf(sv[2],sv[3]));
        #pragma unroll
        for (int off=16; off; off>>=1)
            mx = fmaxf(mx, __shfl_xor_sync(0xffffffffu, mx, off));
        float e[4], sum = 0.f;
        #pragma unroll
        for (int i=0;i<4;i++){ e[i] = __expf(sv[i]-mx); sum += e[i]; }
        #pragma unroll
        for (int off=16; off; off>>=1)
            sum += __shfl_xor_sync(0xffffffffu, sum, off);
        float inv = 1.f / sum;
        #pragma unroll
        for (int i=0;i<4;i++) pm[(lane + 32*i)*8 + w] = e[i]*inv;
    }
    __syncthreads();

    int d0 = tid, d1 = tid + 256;
    float a0[8], a1[8];
    #pragma unroll
    for (int t=0;t<8;t++){ a0[t]=0.f; a1[t]=0.f; }
    for (int s=0; s<NL; s++){
        const float* mrow = mem + (size_t)(bb*NL + s)*ND;
        float m0v = __ldg(mrow + d0);
        float m1v = __ldg(mrow + d1);
        float4 pA = *(const float4*)&pm[s*8];
        float4 pB = *(const float4*)&pm[s*8 + 4];
        a0[0]+=pA.x*m0v; a1[0]+=pA.x*m1v;
        a0[1]+=pA.y*m0v; a1[1]+=pA.y*m1v;
        a0[2]+=pA.z*m0v; a1[2]+=pA.z*m1v;
        a0[3]+=pA.w*m0v; a1[3]+=pA.w*m1v;
        a0[4]+=pB.x*m0v; a1[4]+=pB.x*m1v;
        a0[5]+=pB.y*m0v; a1[5]+=pB.y*m1v;
        a0[6]+=pB.z*m0v; a1[6]+=pB.z*m1v;
        a0[7]+=pB.w*m0v; a1[7]+=pB.w*m1v;
    }
    #pragma unroll
    for (int t=0;t<8;t++){
        float* crow = cO + (size_t)(bb*NL + t0 + t)*ND;
        crow[d0] = a0[t];
        crow[d1] = a1[t];
    }
}

// ================= launch =================
extern "C" void kernel_launch(void* const* d_in, const int* in_sizes, int n_in,
                              void* d_out, int out_size)
{
    const float* cur  = (const float*)d_in[0];
    const float* no   = (const float*)d_in[1];
    const float* Wq   = (const float*)d_in[2];
    const float* bq   = (const float*)d_in[3];
    const float* Wc   = (const float*)d_in[4];
    const float* v    = (const float*)d_in[5];
    const float* Wout = (const float*)d_in[6];
    const float* bout = (const float*)d_in[7];
    const float* mix  = (const float*)d_in[8];
    float* out = (float*)d_out;

    splitT_kernel<<<dim3(ND/32, ND/32),   dim3(32,8)>>>(Wq,   0, ND,   ND);
    splitT_kernel<<<dim3(ND/32, ND/32),   dim3(32,8)>>>(Wc,   1, ND,   ND);
    splitT_kernel<<<dim3(ND/32, 2*ND/32), dim3(32,8)>>>(Wout, 2, 2*ND, ND);

    gemm_proj_kernel<<<dim3(NROWS/128, ND/128, 4), 256, GSMEM>>>(no, cur, bq);

    attn_out1_kernel<<<1152, 256, GSMEM>>>(cur, no, v, bout, mix, out);

    gemm_out2_kernel<<<128, 256, GSMEM>>>(mix, out);
}

// round 10
// speedup vs baseline: 1.6867x; 1.6867x over previous
#include <cuda_runtime.h>
#include <cuda_bf16.h>
#include <cstdint>

#define NB 32
#define NL 128
#define ND 512
#define NROWS (NB*NL)   // 4096

// ================= scratch (device code references ONLY — GB300 ATS trap) =================
__device__ float g_wq_new[NROWS*ND];
__device__ float g_wq_cur[NROWS*ND];
__device__ float g_uh_new[NROWS*ND];
__device__ float g_uh_cur[NROWS*ND];
__device__ float g_c1[NROWS*ND];
__device__ float g_c2[NROWS*ND];

__device__ __nv_bfloat16 g_no_hi [NROWS*ND];
__device__ __nv_bfloat16 g_no_lo [NROWS*ND];
__device__ __nv_bfloat16 g_cur_hi[NROWS*ND];
__device__ __nv_bfloat16 g_cur_lo[NROWS*ND];
__device__ __nv_bfloat16 g_Wqt_hi[ND*ND];      // Wq^T  [N=512][K=512]
__device__ __nv_bfloat16 g_Wqt_lo[ND*ND];
__device__ __nv_bfloat16 g_Wct_hi[ND*ND];
__device__ __nv_bfloat16 g_Wct_lo[ND*ND];
__device__ __nv_bfloat16 g_Wot_hi[ND*2*ND];    // Wout^T [N=512][K=1024]
__device__ __nv_bfloat16 g_Wot_lo[ND*2*ND];
__device__ __nv_bfloat16 g_amix_hi[NROWS*2*ND];// mixed A for out gemm [4096][1024]
__device__ __nv_bfloat16 g_amix_lo[NROWS*2*ND];

// ================= helpers =================
__device__ __forceinline__ uint32_t smem_u32(const void* p){
    uint32_t a;
    asm("{ .reg .u64 t; cvta.to.shared.u64 t, %1; cvt.u32.u64 %0, t; }" : "=r"(a) : "l"(p));
    return a;
}
__device__ __forceinline__ float tanh_apx(float x){
    float y; asm("tanh.approx.f32 %0, %1;" : "=f"(y) : "f"(x)); return y;
}
__device__ __forceinline__ void split2(float x, __nv_bfloat16& h, __nv_bfloat16& l){
    h = __float2bfloat16_rn(x);
    l = __float2bfloat16_rn(x - __bfloat162float(h));
}
__device__ __forceinline__ uint32_t lds32(uint32_t a){
    uint32_t v; asm volatile("ld.shared.b32 %0, [%1];" : "=r"(v) : "r"(a)); return v;
}
__device__ __forceinline__ void mma16816(float* c, const uint32_t* a, const uint32_t* b){
    asm volatile("mma.sync.aligned.m16n8k16.row.col.f32.bf16.bf16.f32 "
        "{%0,%1,%2,%3},{%4,%5,%6,%7},{%8,%9},{%0,%1,%2,%3};"
        : "+f"(c[0]),"+f"(c[1]),"+f"(c[2]),"+f"(c[3])
        : "r"(a[0]),"r"(a[1]),"r"(a[2]),"r"(a[3]),"r"(b[0]),"r"(b[1]));
}

// ================= convert kernels (selector-based) =================
__global__ void __launch_bounds__(256) split_kernel(const float* __restrict__ in, int which)
{
    __nv_bfloat16* hi = which ? g_cur_hi : g_no_hi;
    __nv_bfloat16* lo = which ? g_cur_lo : g_no_lo;
    int i = blockIdx.x*256 + threadIdx.x;
    float4 v = ((const float4*)in)[i];
    __nv_bfloat16 h0,l0,h1,l1,h2,l2,h3,l3;
    split2(v.x,h0,l0); split2(v.y,h1,l1); split2(v.z,h2,l2); split2(v.w,h3,l3);
    __nv_bfloat162* H = (__nv_bfloat162*)hi; __nv_bfloat162* L = (__nv_bfloat162*)lo;
    H[2*i]   = __nv_bfloat162(h0,h1); H[2*i+1] = __nv_bfloat162(h2,h3);
    L[2*i]   = __nv_bfloat162(l0,l1); L[2*i+1] = __nv_bfloat162(l2,l3);
}

// in[R][C] fp32 -> out[C][R] hi/lo bf16 (transpose+split). grid (C/32, R/32), block (32,8)
__global__ void __launch_bounds__(256) splitT_kernel(
    const float* __restrict__ in, int which, int R, int C)
{
    __nv_bfloat16 *hi, *lo;
    if      (which == 0){ hi = g_Wqt_hi; lo = g_Wqt_lo; }
    else if (which == 1){ hi = g_Wct_hi; lo = g_Wct_lo; }
    else                { hi = g_Wot_hi; lo = g_Wot_lo; }
    __shared__ float t[32][33];
    int bx = blockIdx.x*32, by = blockIdx.y*32;
    int x = threadIdx.x, y = threadIdx.y;
    #pragma unroll
    for (int i=0;i<32;i+=8)
        t[y+i][x] = in[(size_t)(by+y+i)*C + bx + x];
    __syncthreads();
    #pragma unroll
    for (int i=0;i<32;i+=8){
        float v = t[x][y+i];
        __nv_bfloat16 h,l; split2(v,h,l);
        size_t o = (size_t)(bx+y+i)*R + by + x;
        hi[o]=h; lo[o]=l;
    }
}

__global__ void __launch_bounds__(256) mix_split_kernel(
    const float* __restrict__ no, const float* __restrict__ cur, const float* __restrict__ mixp)
{
    float m = __ldg(mixp);
    int i = blockIdx.x*256 + threadIdx.x;
    int r = i >> 8;
    int col = (i & 255)*4;
    const float *p1,*p2; int sc;
    if (col < ND){ p1=g_c1; p2=g_c2; sc=col; } else { p1=no; p2=cur; sc=col-ND; }
    float4 a = *(const float4*)(p1 + (size_t)r*ND + sc);
    float4 b = *(const float4*)(p2 + (size_t)r*ND + sc);
    float4 w;
    w.x=a.x+m*(b.x-a.x); w.y=a.y+m*(b.y-a.y); w.z=a.z+m*(b.z-a.z); w.w=a.w+m*(b.w-a.w);
    __nv_bfloat16 h0,l0,h1,l1,h2,l2,h3,l3;
    split2(w.x,h0,l0); split2(w.y,h1,l1); split2(w.z,h2,l2); split2(w.w,h3,l3);
    size_t o = (size_t)r*2*ND + col;
    *(__nv_bfloat162*)(g_amix_hi+o)   = __nv_bfloat162(h0,h1);
    *(__nv_bfloat162*)(g_amix_hi+o+2) = __nv_bfloat162(h2,h3);
    *(__nv_bfloat162*)(g_amix_lo+o)   = __nv_bfloat162(l0,l1);
    *(__nv_bfloat162*)(g_amix_lo+o+2) = __nv_bfloat162(l2,l3);
}

// ================= mma.sync split-bf16 GEMM (R8-verified) =================
#define BK    32
#define LDSW  40                 // padded row length (bf16 elems): 80B stride
#define MATE  (128*LDSW)         // elems per matrix tile (5120)
#define GSMEM (4*MATE*2)         // 40960 B

__device__ __forceinline__ void gemm_body(
    const __nv_bfloat16* __restrict__ Ahi, const __nv_bfloat16* __restrict__ Alo,
    const __nv_bfloat16* __restrict__ Bhi, const __nv_bfloat16* __restrict__ Blo,
    int K, const float* __restrict__ bias, float* __restrict__ C, int ldc)
{
    extern __shared__ __nv_bfloat16 sm[];
    uint32_t sb = smem_u32(sm);
    int tid = threadIdx.x, lane = tid & 31, wid = tid >> 5;
    int wm = wid & 1, wn = wid >> 1;
    int m0 = blockIdx.x*128, n0 = blockIdx.y*128;
    int g = lane >> 2, tig = lane & 3;

    const __nv_bfloat16* gp[4] = {Ahi, Alo, Bhi, Blo};
    const int rb[4] = {m0, m0, n0, n0};

    float acc[4][4][4];
    #pragma unroll
    for (int i=0;i<4;i++)
        #pragma unroll
        for (int j=0;j<4;j++)
            #pragma unroll
            for (int k=0;k<4;k++) acc[i][j][k]=0.f;

    const int chunks = K / BK;
    uint4 stg[8];

    #pragma unroll
    for (int i=0;i<8;i++){
        const int mat = i>>1;
        int cc = tid + (i&1)*256, row = cc>>2, kc = cc&3;
        stg[i] = *(const uint4*)(gp[mat] + (size_t)(rb[mat]+row)*K + kc*8);
    }

    for (int c = 0; c < chunks; c++){
        __syncthreads();
        #pragma unroll
        for (int i=0;i<8;i++){
            const int mat = i>>1;
            int cc = tid + (i&1)*256, row = cc>>2, kc = cc&3;
            *(uint4*)(sm + mat*MATE + row*LDSW + kc*8) = stg[i];
        }
        __syncthreads();
        if (c+1 < chunks){
            int k0 = (c+1)*BK;
            #pragma unroll
            for (int i=0;i<8;i++){
                const int mat = i>>1;
                int cc = tid + (i&1)*256, row = cc>>2, kc = cc&3;
                stg[i] = *(const uint4*)(gp[mat] + (size_t)(rb[mat]+row)*K + k0 + kc*8);
            }
        }

        #pragma unroll
        for (int ks=0; ks<2; ks++){
            uint32_t ah[4][4], al[4][4], bh[4][2], bl[4][2];
            #pragma unroll
            for (int mt=0;mt<4;mt++){
                uint32_t o00 = (uint32_t)((wm*64 + mt*16 + g)*LDSW + ks*16 + tig*2)*2;
                uint32_t o10 = o00 + 8*LDSW*2;
                uint32_t aH = sb + 0*MATE*2, aL = sb + 1*MATE*2;
                ah[mt][0] = lds32(aH + o00);
                ah[mt][1] = lds32(aH + o10);
                ah[mt][2] = lds32(aH + o00 + 16);
                ah[mt][3] = lds32(aH + o10 + 16);
                al[mt][0] = lds32(aL + o00);
                al[mt][1] = lds32(aL + o10);
                al[mt][2] = lds32(aL + o00 + 16);
                al[mt][3] = lds32(aL + o10 + 16);
            }
            #pragma unroll
            for (int nt=0;nt<4;nt++){
                uint32_t o0 = (uint32_t)((wn*32 + nt*8 + g)*LDSW + ks*16 + tig*2)*2;
                uint32_t bH = sb + 2*MATE*2, bL = sb + 3*MATE*2;
                bh[nt][0] = lds32(bH + o0);
                bh[nt][1] = lds32(bH + o0 + 16);
                bl[nt][0] = lds32(bL + o0);
                bl[nt][1] = lds32(bL + o0 + 16);
            }
            #pragma unroll
            for (int mt=0;mt<4;mt++)
                #pragma unroll
                for (int nt=0;nt<4;nt++){
                    mma16816(acc[mt][nt], ah[mt], bh[nt]);
                    mma16816(acc[mt][nt], ah[mt], bl[nt]);
                    mma16816(acc[mt][nt], al[mt], bh[nt]);
                }
        }
    }

    int t2 = tig*2;
    #pragma unroll
    for (int mt=0;mt<4;mt++){
        int m = m0 + wm*64 + mt*16 + g;
        #pragma unroll
        for (int nt=0;nt<4;nt++){
            int n = n0 + wn*32 + nt*8 + t2;
            float b0v = bias ? bias[n]   : 0.f;
            float b1v = bias ? bias[n+1] : 0.f;
            float2 r0; r0.x = acc[mt][nt][0] + b0v; r0.y = acc[mt][nt][1] + b1v;
            float2 r1; r1.x = acc[mt][nt][2] + b0v; r1.y = acc[mt][nt][3] + b1v;
            *(float2*)(C + (size_t)m*ldc + n)     = r0;
            *(float2*)(C + (size_t)(m+8)*ldc + n) = r1;
        }
    }
}

__global__ void __launch_bounds__(256,1) gemm_proj_kernel(const float* __restrict__ bq){
    int combo = blockIdx.z;
    const __nv_bfloat16 *Ah,*Al,*Bh,*Bl; const float* bias; float* C;
    switch (combo){
    case 0: Ah=g_no_hi;  Al=g_no_lo;  Bh=g_Wqt_hi; Bl=g_Wqt_lo; bias=bq;      C=g_wq_new; break;
    case 1: Ah=g_cur_hi; Al=g_cur_lo; Bh=g_Wqt_hi; Bl=g_Wqt_lo; bias=bq;      C=g_wq_cur; break;
    case 2: Ah=g_no_hi;  Al=g_no_lo;  Bh=g_Wct_hi; Bl=g_Wct_lo; bias=nullptr; C=g_uh_new; break;
    default:Ah=g_cur_hi; Al=g_cur_lo; Bh=g_Wct_hi; Bl=g_Wct_lo; bias=nullptr; C=g_uh_cur; break;
    }
    gemm_body(Ah, Al, Bh, Bl, ND, bias, C, ND);
}

__global__ void __launch_bounds__(256,1) gemm_out_kernel(const float* __restrict__ bout, float* __restrict__ out){
    gemm_body(g_amix_hi, g_amix_lo, g_Wot_hi, g_Wot_lo, 2*ND, bout, out, ND);
}

// ================= fused attention: 2 t-rows per warp =================
// Block covers 16 t-rows; warp w owns rows t0+w and t0+w+8 (each u-load feeds 32 tanh).
__global__ void __launch_bounds__(256) attn_kernel(
    const float* __restrict__ cur, const float* __restrict__ no,
    const float* __restrict__ v)
{
    __shared__ float sc[16][128];    // raw scores [t][s]
    __shared__ float pm[128][16];    // probabilities [s][t]

    int dir = blockIdx.z;
    int bb  = blockIdx.y;
    int t0  = blockIdx.x * 16;
    const float* wq  = dir ? g_wq_cur : g_wq_new;
    const float* uh  = dir ? g_uh_new : g_uh_cur;
    const float* mem = dir ? no       : cur;
    float*       cO  = dir ? g_c2     : g_c1;

    int tid = threadIdx.x, w = tid >> 5, lane = tid & 31;

    // ---- phase 1: scores for rows t0+w and t0+w+8
    float4 v4[4], qa[4], qb[4];
    {
        const float* ra = wq + (size_t)(bb*NL + t0 + w)*ND;
        const float* rb = wq + (size_t)(bb*NL + t0 + w + 8)*ND;
        #pragma unroll
        for (int i=0;i<4;i++){
            v4[i] = *(const float4*)(v  + lane*4 + 128*i);
            qa[i] = *(const float4*)(ra + lane*4 + 128*i);
            qb[i] = *(const float4*)(rb + lane*4 + 128*i);
        }
    }
    for (int s=0; s<NL; s++){
        const float* urow = uh + (size_t)(bb*NL + s)*ND;
        float acca = 0.f, accb = 0.f;
        #pragma unroll
        for (int i=0;i<4;i++){
            float4 u = *(const float4*)(urow + lane*4 + 128*i);
            acca += v4[i].x * tanh_apx(qa[i].x + u.x);
            accb += v4[i].x * tanh_apx(qb[i].x + u.x);
            acca += v4[i].y * tanh_apx(qa[i].y + u.y);
            accb += v4[i].y * tanh_apx(qb[i].y + u.y);
            acca += v4[i].z * tanh_apx(qa[i].z + u.z);
            accb += v4[i].z * tanh_apx(qb[i].z + u.z);
            acca += v4[i].w * tanh_apx(qa[i].w + u.w);
            accb += v4[i].w * tanh_apx(qb[i].w + u.w);
        }
        #pragma unroll
        for (int off=16; off; off>>=1){
            acca += __shfl_xor_sync(0xffffffffu, acca, off);
            accb += __shfl_xor_sync(0xffffffffu, accb, off);
        }
        if (lane == 0){ sc[w][s] = acca; sc[w+8][s] = accb; }
    }
    __syncwarp();

    // ---- phase 2: softmax for both rows
    #pragma unroll
    for (int rr=0; rr<2; rr++){
        int r = w + rr*8;
        float sv[4];
        #pragma unroll
        for (int i=0;i<4;i++) sv[i] = sc[r][lane + 32*i];
        float mx = fmaxf(fmaxf(sv[0],sv[1]), fmaxf(sv[2],sv[3]));
        #pragma unroll
        for (int off=16; off; off>>=1)
            mx = fmaxf(mx, __shfl_xor_sync(0xffffffffu, mx, off));
        float e[4], sum = 0.f;
        #pragma unroll
        for (int i=0;i<4;i++){ e[i] = __expf(sv[i]-mx); sum += e[i]; }
        #pragma unroll
        for (int off=16; off; off>>=1)
            sum += __shfl_xor_sync(0xffffffffu, sum, off);
        float inv = 1.f / sum;
        #pragma unroll
        for (int i=0;i<4;i++) pm[lane + 32*i][r] = e[i]*inv;
    }
    __syncthreads();

    // ---- phase 3: context for 16 rows; thread owns cols d0=tid, d1=tid+256
    int d0 = tid, d1 = tid + 256;
    float a0[16], a1[16];
    #pragma unroll
    for (int t=0;t<16;t++){ a0[t]=0.f; a1[t]=0.f; }
    for (int s=0; s<NL; s++){
        const float* mrow = mem + (size_t)(bb*NL + s)*ND;
        float m0v = __ldg(mrow + d0);
        float m1v = __ldg(mrow + d1);
        #pragma unroll
        for (int q4i=0;q4i<4;q4i++){
            float4 p = *(const float4*)&pm[s][q4i*4];
            a0[q4i*4+0]+=p.x*m0v; a1[q4i*4+0]+=p.x*m1v;
            a0[q4i*4+1]+=p.y*m0v; a1[q4i*4+1]+=p.y*m1v;
            a0[q4i*4+2]+=p.z*m0v; a1[q4i*4+2]+=p.z*m1v;
            a0[q4i*4+3]+=p.w*m0v; a1[q4i*4+3]+=p.w*m1v;
        }
    }
    #pragma unroll
    for (int t=0;t<16;t++){
        float* crow = cO + (size_t)(bb*NL + t0 + t)*ND;
        crow[d0] = a0[t];
        crow[d1] = a1[t];
    }
}

// ================= launch =================
extern "C" void kernel_launch(void* const* d_in, const int* in_sizes, int n_in,
                              void* d_out, int out_size)
{
    const float* cur  = (const float*)d_in[0];
    const float* no   = (const float*)d_in[1];
    const float* Wq   = (const float*)d_in[2];
    const float* bq   = (const float*)d_in[3];
    const float* Wc   = (const float*)d_in[4];
    const float* v    = (const float*)d_in[5];
    const float* Wout = (const float*)d_in[6];
    const float* bout = (const float*)d_in[7];
    const float* mix  = (const float*)d_in[8];
    float* out = (float*)d_out;

    split_kernel<<<2048, 256>>>(no,  0);
    split_kernel<<<2048, 256>>>(cur, 1);
    splitT_kernel<<<dim3(ND/32, ND/32),   dim3(32,8)>>>(Wq,   0, ND,   ND);
    splitT_kernel<<<dim3(ND/32, ND/32),   dim3(32,8)>>>(Wc,   1, ND,   ND);
    splitT_kernel<<<dim3(ND/32, 2*ND/32), dim3(32,8)>>>(Wout, 2, 2*ND, ND);

    gemm_proj_kernel<<<dim3(NROWS/128, ND/128, 4), 256, GSMEM>>>(bq);

    attn_kernel<<<dim3(NL/16, NB, 2), 256>>>(cur, no, v);

    mix_split_kernel<<<NROWS*2*ND/(4*256), 256>>>(no, cur, mix);
    gemm_out_kernel<<<dim3(NROWS/128, ND/128), 256, GSMEM>>>(bout, out);
}

// round 11
// speedup vs baseline: 1.7735x; 1.0514x over previous
#include <cuda_runtime.h>
#include <cuda_bf16.h>
#include <cstdint>

#define NB 32
#define NL 128
#define ND 512
#define NROWS (NB*NL)   // 4096

// ================= scratch (device code references ONLY — GB300 ATS trap) =================
__device__ float g_wq_new[NROWS*ND];
__device__ float g_wq_cur[NROWS*ND];
__device__ float g_uh_new[NROWS*ND];
__device__ float g_uh_cur[NROWS*ND];
__device__ float g_c1[NROWS*ND];
__device__ float g_c2[NROWS*ND];

__device__ __nv_bfloat16 g_no_hi [NROWS*ND];
__device__ __nv_bfloat16 g_no_lo [NROWS*ND];
__device__ __nv_bfloat16 g_cur_hi[NROWS*ND];
__device__ __nv_bfloat16 g_cur_lo[NROWS*ND];
__device__ __nv_bfloat16 g_Wqt_hi[ND*ND];      // Wq^T  [N=512][K=512]
__device__ __nv_bfloat16 g_Wqt_lo[ND*ND];
__device__ __nv_bfloat16 g_Wct_hi[ND*ND];
__device__ __nv_bfloat16 g_Wct_lo[ND*ND];
__device__ __nv_bfloat16 g_Wot_hi[ND*2*ND];    // Wout^T [N=512][K=1024]
__device__ __nv_bfloat16 g_Wot_lo[ND*2*ND];
__device__ __nv_bfloat16 g_amix_hi[NROWS*2*ND];// mixed A for out gemm [4096][1024]
__device__ __nv_bfloat16 g_amix_lo[NROWS*2*ND];

// ================= helpers =================
__device__ __forceinline__ uint32_t smem_u32(const void* p){
    uint32_t a;
    asm("{ .reg .u64 t; cvta.to.shared.u64 t, %1; cvt.u32.u64 %0, t; }" : "=r"(a) : "l"(p));
    return a;
}
__device__ __forceinline__ float tanh_apx(float x){
    float y; asm("tanh.approx.f32 %0, %1;" : "=f"(y) : "f"(x)); return y;
}
__device__ __forceinline__ void split2(float x, __nv_bfloat16& h, __nv_bfloat16& l){
    h = __float2bfloat16_rn(x);
    l = __float2bfloat16_rn(x - __bfloat162float(h));
}
__device__ __forceinline__ uint32_t lds32(uint32_t a){
    uint32_t v; asm volatile("ld.shared.b32 %0, [%1];" : "=r"(v) : "r"(a)); return v;
}
__device__ __forceinline__ void mma16816(float* c, const uint32_t* a, const uint32_t* b){
    asm volatile("mma.sync.aligned.m16n8k16.row.col.f32.bf16.bf16.f32 "
        "{%0,%1,%2,%3},{%4,%5,%6,%7},{%8,%9},{%0,%1,%2,%3};"
        : "+f"(c[0]),"+f"(c[1]),"+f"(c[2]),"+f"(c[3])
        : "r"(a[0]),"r"(a[1]),"r"(a[2]),"r"(a[3]),"r"(b[0]),"r"(b[1]));
}

// ================= convert kernels (selector-based) =================
__global__ void __launch_bounds__(256) split_kernel(const float* __restrict__ in, int which)
{
    __nv_bfloat16* hi = which ? g_cur_hi : g_no_hi;
    __nv_bfloat16* lo = which ? g_cur_lo : g_no_lo;
    int i = blockIdx.x*256 + threadIdx.x;
    float4 v = ((const float4*)in)[i];
    __nv_bfloat16 h0,l0,h1,l1,h2,l2,h3,l3;
    split2(v.x,h0,l0); split2(v.y,h1,l1); split2(v.z,h2,l2); split2(v.w,h3,l3);
    __nv_bfloat162* H = (__nv_bfloat162*)hi; __nv_bfloat162* L = (__nv_bfloat162*)lo;
    H[2*i]   = __nv_bfloat162(h0,h1); H[2*i+1] = __nv_bfloat162(h2,h3);
    L[2*i]   = __nv_bfloat162(l0,l1); L[2*i+1] = __nv_bfloat162(l2,l3);
}

// in[R][C] fp32 -> out[C][R] hi/lo bf16 (transpose+split). grid (C/32, R/32), block (32,8)
__global__ void __launch_bounds__(256) splitT_kernel(
    const float* __restrict__ in, int which, int R, int C)
{
    __nv_bfloat16 *hi, *lo;
    if      (which == 0){ hi = g_Wqt_hi; lo = g_Wqt_lo; }
    else if (which == 1){ hi = g_Wct_hi; lo = g_Wct_lo; }
    else                { hi = g_Wot_hi; lo = g_Wot_lo; }
    __shared__ float t[32][33];
    int bx = blockIdx.x*32, by = blockIdx.y*32;
    int x = threadIdx.x, y = threadIdx.y;
    #pragma unroll
    for (int i=0;i<32;i+=8)
        t[y+i][x] = in[(size_t)(by+y+i)*C + bx + x];
    __syncthreads();
    #pragma unroll
    for (int i=0;i<32;i+=8){
        float v = t[x][y+i];
        __nv_bfloat16 h,l; split2(v,h,l);
        size_t o = (size_t)(bx+y+i)*R + by + x;
        hi[o]=h; lo[o]=l;
    }
}

__global__ void __launch_bounds__(256) mix_split_kernel(
    const float* __restrict__ no, const float* __restrict__ cur, const float* __restrict__ mixp)
{
    float m = __ldg(mixp);
    int i = blockIdx.x*256 + threadIdx.x;
    int r = i >> 8;
    int col = (i & 255)*4;
    const float *p1,*p2; int sc;
    if (col < ND){ p1=g_c1; p2=g_c2; sc=col; } else { p1=no; p2=cur; sc=col-ND; }
    float4 a = *(const float4*)(p1 + (size_t)r*ND + sc);
    float4 b = *(const float4*)(p2 + (size_t)r*ND + sc);
    float4 w;
    w.x=a.x+m*(b.x-a.x); w.y=a.y+m*(b.y-a.y); w.z=a.z+m*(b.z-a.z); w.w=a.w+m*(b.w-a.w);
    __nv_bfloat16 h0,l0,h1,l1,h2,l2,h3,l3;
    split2(w.x,h0,l0); split2(w.y,h1,l1); split2(w.z,h2,l2); split2(w.w,h3,l3);
    size_t o = (size_t)r*2*ND + col;
    *(__nv_bfloat162*)(g_amix_hi+o)   = __nv_bfloat162(h0,h1);
    *(__nv_bfloat162*)(g_amix_hi+o+2) = __nv_bfloat162(h2,h3);
    *(__nv_bfloat162*)(g_amix_lo+o)   = __nv_bfloat162(l0,l1);
    *(__nv_bfloat162*)(g_amix_lo+o+2) = __nv_bfloat162(l2,l3);
}

// ================= mma.sync split-bf16 GEMM: 4 warps, warp tile 64x64 =================
// CTA 128x128, 128 threads. warp (wm=wid&1, wn=wid>>1) owns 64x64.
// Per chunk LDS traffic 64KB vs 768 warp-mma -> tensor-bound (was SMEM-bound at 64x32).
#define BK    32
#define LDSW  40                 // padded row length (bf16 elems): 80B stride, conflict-free
#define MATE  (128*LDSW)         // elems per matrix tile (5120)
#define GSMEM (4*MATE*2)         // 40960 B

__device__ __forceinline__ void gemm_body(
    const __nv_bfloat16* __restrict__ Ahi, const __nv_bfloat16* __restrict__ Alo,
    const __nv_bfloat16* __restrict__ Bhi, const __nv_bfloat16* __restrict__ Blo,
    int K, const float* __restrict__ bias, float* __restrict__ C, int ldc)
{
    extern __shared__ __nv_bfloat16 sm[];
    uint32_t sb = smem_u32(sm);
    int tid = threadIdx.x, lane = tid & 31, wid = tid >> 5;
    int wm = wid & 1, wn = wid >> 1;          // wn in {0,1}
    int m0 = blockIdx.x*128, n0 = blockIdx.y*128;
    int g = lane >> 2, tig = lane & 3;

    const __nv_bfloat16* gp[4] = {Ahi, Alo, Bhi, Blo};
    const int rb[4] = {m0, m0, n0, n0};

    float acc[4][8][4];
    #pragma unroll
    for (int i=0;i<4;i++)
        #pragma unroll
        for (int j=0;j<8;j++)
            #pragma unroll
            for (int k=0;k<4;k++) acc[i][j][k]=0.f;

    const int chunks = K / BK;

    for (int c = 0; c < chunks; c++){
        int k0 = c*BK;
        __syncthreads();   // previous chunk's compute done reading smem
        // load 4x(128 rows x 32 k) bf16: 2048 uint4, 16 per thread
        #pragma unroll
        for (int i=0;i<16;i++){
            const int mat = i >> 2;
            int idx = tid + (i & 3)*128;        // 0..511 per matrix
            int row = idx >> 2, kc = idx & 3;
            uint4 v = *(const uint4*)(gp[mat] + (size_t)(rb[mat]+row)*K + k0 + kc*8);
            *(uint4*)(sm + mat*MATE + row*LDSW + kc*8) = v;
        }
        __syncthreads();

        #pragma unroll
        for (int ks=0; ks<2; ks++){
            uint32_t ah[4][4], al[4][4];
            // A frags: a0=(g,2t) a1=(g+8,2t) a2=(g,2t+8) a3=(g+8,2t+8)
            #pragma unroll
            for (int mt=0;mt<4;mt++){
                uint32_t o00 = (uint32_t)((wm*64 + mt*16 + g)*LDSW + ks*16 + tig*2)*2;
                uint32_t o10 = o00 + 8*LDSW*2;
                uint32_t aH = sb + 0*MATE*2, aL = sb + 1*MATE*2;
                ah[mt][0] = lds32(aH + o00);
                ah[mt][1] = lds32(aH + o10);
                ah[mt][2] = lds32(aH + o00 + 16);
                ah[mt][3] = lds32(aH + o10 + 16);
                al[mt][0] = lds32(aL + o00);
                al[mt][1] = lds32(aL + o10);
                al[mt][2] = lds32(aL + o00 + 16);
                al[mt][3] = lds32(aL + o10 + 16);
            }
            // B frags (B^T stored [n][k]): b0=(k=2t,n=g) b1=(k=2t+8,n=g)
            #pragma unroll
            for (int nt=0;nt<8;nt++){
                uint32_t o0 = (uint32_t)((wn*64 + nt*8 + g)*LDSW + ks*16 + tig*2)*2;
                uint32_t bH = sb + 2*MATE*2, bL = sb + 3*MATE*2;
                uint32_t bh[2], bl[2];
                bh[0] = lds32(bH + o0);
                bh[1] = lds32(bH + o0 + 16);
                bl[0] = lds32(bL + o0);
                bl[1] = lds32(bL + o0 + 16);
                #pragma unroll
                for (int mt=0;mt<4;mt++){
                    mma16816(acc[mt][nt], ah[mt], bh);
                    mma16816(acc[mt][nt], ah[mt], bl);
                    mma16816(acc[mt][nt], al[mt], bh);
                }
            }
        }
    }

    // epilogue: c0,c1 -> (g, 2t..2t+1); c2,c3 -> (g+8, 2t..2t+1)
    int t2 = tig*2;
    #pragma unroll
    for (int mt=0;mt<4;mt++){
        int m = m0 + wm*64 + mt*16 + g;
        #pragma unroll
        for (int nt=0;nt<8;nt++){
            int n = n0 + wn*64 + nt*8 + t2;
            float b0v = bias ? bias[n]   : 0.f;
            float b1v = bias ? bias[n+1] : 0.f;
            float2 r0; r0.x = acc[mt][nt][0] + b0v; r0.y = acc[mt][nt][1] + b1v;
            float2 r1; r1.x = acc[mt][nt][2] + b0v; r1.y = acc[mt][nt][3] + b1v;
            *(float2*)(C + (size_t)m*ldc + n)     = r0;
            *(float2*)(C + (size_t)(m+8)*ldc + n) = r1;
        }
    }
}

__global__ void __launch_bounds__(128) gemm_proj_kernel(const float* __restrict__ bq){
    int combo = blockIdx.z;
    const __nv_bfloat16 *Ah,*Al,*Bh,*Bl; const float* bias; float* C;
    switch (combo){
    case 0: Ah=g_no_hi;  Al=g_no_lo;  Bh=g_Wqt_hi; Bl=g_Wqt_lo; bias=bq;      C=g_wq_new; break;
    case 1: Ah=g_cur_hi; Al=g_cur_lo; Bh=g_Wqt_hi; Bl=g_Wqt_lo; bias=bq;      C=g_wq_cur; break;
    case 2: Ah=g_no_hi;  Al=g_no_lo;  Bh=g_Wct_hi; Bl=g_Wct_lo; bias=nullptr; C=g_uh_new; break;
    default:Ah=g_cur_hi; Al=g_cur_lo; Bh=g_Wct_hi; Bl=g_Wct_lo; bias=nullptr; C=g_uh_cur; break;
    }
    gemm_body(Ah, Al, Bh, Bl, ND, bias, C, ND);
}

__global__ void __launch_bounds__(128) gemm_out_kernel(const float* __restrict__ bout, float* __restrict__ out){
    gemm_body(g_amix_hi, g_amix_lo, g_Wot_hi, g_Wot_lo, 2*ND, bout, out, ND);
}

// ================= fused attention: 2 t-rows per warp (R10-proven) =================
__global__ void __launch_bounds__(256) attn_kernel(
    const float* __restrict__ cur, const float* __restrict__ no,
    const float* __restrict__ v)
{
    __shared__ float sc[16][128];
    __shared__ float pm[128][16];

    int dir = blockIdx.z;
    int bb  = blockIdx.y;
    int t0  = blockIdx.x * 16;
    const float* wq  = dir ? g_wq_cur : g_wq_new;
    const float* uh  = dir ? g_uh_new : g_uh_cur;
    const float* mem = dir ? no       : cur;
    float*       cO  = dir ? g_c2     : g_c1;

    int tid = threadIdx.x, w = tid >> 5, lane = tid & 31;

    float4 v4[4], qa[4], qb[4];
    {
        const float* ra = wq + (size_t)(bb*NL + t0 + w)*ND;
        const float* rb = wq + (size_t)(bb*NL + t0 + w + 8)*ND;
        #pragma unroll
        for (int i=0;i<4;i++){
            v4[i] = *(const float4*)(v  + lane*4 + 128*i);
            qa[i] = *(const float4*)(ra + lane*4 + 128*i);
            qb[i] = *(const float4*)(rb + lane*4 + 128*i);
        }
    }
    for (int s=0; s<NL; s++){
        const float* urow = uh + (size_t)(bb*NL + s)*ND;
        float acca = 0.f, accb = 0.f;
        #pragma unroll
        for (int i=0;i<4;i++){
            float4 u = *(const float4*)(urow + lane*4 + 128*i);
            acca += v4[i].x * tanh_apx(qa[i].x + u.x);
            accb += v4[i].x * tanh_apx(qb[i].x + u.x);
            acca += v4[i].y * tanh_apx(qa[i].y + u.y);
            accb += v4[i].y * tanh_apx(qb[i].y + u.y);
            acca += v4[i].z * tanh_apx(qa[i].z + u.z);
            accb += v4[i].z * tanh_apx(qb[i].z + u.z);
            acca += v4[i].w * tanh_apx(qa[i].w + u.w);
            accb += v4[i].w * tanh_apx(qb[i].w + u.w);
        }
        #pragma unroll
        for (int off=16; off; off>>=1){
            acca += __shfl_xor_sync(0xffffffffu, acca, off);
            accb += __shfl_xor_sync(0xffffffffu, accb, off);
        }
        if (lane == 0){ sc[w][s] = acca; sc[w+8][s] = accb; }
    }
    __syncwarp();

    #pragma unroll
    for (int rr=0; rr<2; rr++){
        int r = w + rr*8;
        float sv[4];
        #pragma unroll
        for (int i=0;i<4;i++) sv[i] = sc[r][lane + 32*i];
        float mx = fmaxf(fmaxf(sv[0],sv[1]), fmaxf(sv[2],sv[3]));
        #pragma unroll
        for (int off=16; off; off>>=1)
            mx = fmaxf(mx, __shfl_xor_sync(0xffffffffu, mx, off));
        float e[4], sum = 0.f;
        #pragma unroll
        for (int i=0;i<4;i++){ e[i] = __expf(sv[i]-mx); sum += e[i]; }
        #pragma unroll
        for (int off=16; off; off>>=1)
            sum += __shfl_xor_sync(0xffffffffu, sum, off);
        float inv = 1.f / sum;
        #pragma unroll
        for (int i=0;i<4;i++) pm[lane + 32*i][r] = e[i]*inv;
    }
    __syncthreads();

    int d0 = tid, d1 = tid + 256;
    float a0[16], a1[16];
    #pragma unroll
    for (int t=0;t<16;t++){ a0[t]=0.f; a1[t]=0.f; }
    for (int s=0; s<NL; s++){
        const float* mrow = mem + (size_t)(bb*NL + s)*ND;
        float m0v = __ldg(mrow + d0);
        float m1v = __ldg(mrow + d1);
        #pragma unroll
        for (int q4i=0;q4i<4;q4i++){
            float4 p = *(const float4*)&pm[s][q4i*4];
            a0[q4i*4+0]+=p.x*m0v; a1[q4i*4+0]+=p.x*m1v;
            a0[q4i*4+1]+=p.y*m0v; a1[q4i*4+1]+=p.y*m1v;
            a0[q4i*4+2]+=p.z*m0v; a1[q4i*4+2]+=p.z*m1v;
            a0[q4i*4+3]+=p.w*m0v; a1[q4i*4+3]+=p.w*m1v;
        }
    }
    #pragma unroll
    for (int t=0;t<16;t++){
        float* crow = cO + (size_t)(bb*NL + t0 + t)*ND;
        crow[d0] = a0[t];
        crow[d1] = a1[t];
    }
}

// ================= launch =================
extern "C" void kernel_launch(void* const* d_in, const int* in_sizes, int n_in,
                              void* d_out, int out_size)
{
    const float* cur  = (const float*)d_in[0];
    const float* no   = (const float*)d_in[1];
    const float* Wq   = (const float*)d_in[2];
    const float* bq   = (const float*)d_in[3];
    const float* Wc   = (const float*)d_in[4];
    const float* v    = (const float*)d_in[5];
    const float* Wout = (const float*)d_in[6];
    const float* bout = (const float*)d_in[7];
    const float* mix  = (const float*)d_in[8];
    float* out = (float*)d_out;

    split_kernel<<<2048, 256>>>(no,  0);
    split_kernel<<<2048, 256>>>(cur, 1);
    splitT_kernel<<<dim3(ND/32, ND/32),   dim3(32,8)>>>(Wq,   0, ND,   ND);
    splitT_kernel<<<dim3(ND/32, ND/32),   dim3(32,8)>>>(Wc,   1, ND,   ND);
    splitT_kernel<<<dim3(ND/32, 2*ND/32), dim3(32,8)>>>(Wout, 2, 2*ND, ND);

    gemm_proj_kernel<<<dim3(NROWS/128, ND/128, 4), 128, GSMEM>>>(bq);

    attn_kernel<<<dim3(NL/16, NB, 2), 256>>>(cur, no, v);

    mix_split_kernel<<<NROWS*2*ND/(4*256), 256>>>(no, cur, mix);
    gemm_out_kernel<<<dim3(NROWS/128, ND/128), 128, GSMEM>>>(bout, out);
}